// round 10
// baseline (speedup 1.0000x reference)
#include <cuda_runtime.h>
#include <math.h>

#define BB   512
#define SS   1024
#define KK   50
#define MM   50
#define VV   200
#define AA   64
#define TWOA 128
#define NB   4
#define NBLK (BB / NB)     // 128 CTAs
#define NTHR 800           // 25 warps

// ---- kernel2 dynamic shared layout (float offsets) ----
#define OFF_WE  0                        // 25600 (We rows)
#define OFF_WR  (OFF_WE + VV*TWOA)       // 13312 (Wr rows padded to 208)
#define OFF_W   (OFF_WR + AA*208)        // 2*4*52 double-buffered w
#define OFF_AT  (OFF_W  + 2*NB*52)       // 2*256 double-buffered att
#define OFF_RC  (OFF_AT + 2*NB*AA)       // 256
#define OFF_R   (OFF_RC + NB*AA)         // 800
#define OFF_ER  (OFF_R  + NB*VV)         // 800
#define OFF_AR  (OFF_ER + NB*VV + 8)     // 800 (+8 pad: conflict-free dual stores)
#define OFF_BR  (OFF_AR + NB*VV)         // 64
#define OFF_BE  (OFF_BR + AA)            // 200
#define OFF_BA  (OFF_BE + VV)            // 200
#define SMEM2_FLOATS (OFF_BA + VV)
#define SMEM2_BYTES  (SMEM2_FLOATS * 4)

// Output offsets (floats) in concatenated flat output
#define OUT_RC  0ULL                                        // (B,S,A)
#define OUT_MEM ((unsigned long long)BB * SS * AA)          // (B,M,V)
#define OUT_W   (OUT_MEM + (unsigned long long)BB*MM*VV)    // (B,S,M)

// ---- packed f32x2 helpers ----
typedef unsigned long long u64;

__device__ __forceinline__ u64 pk2(float lo, float hi) {
    u64 d; asm("mov.b64 %0, {%1, %2};" : "=l"(d) : "f"(lo), "f"(hi)); return d;
}
__device__ __forceinline__ float unlo(u64 v) {
    float f; asm("{ .reg .f32 t; mov.b64 {%0, t}, %1; }" : "=f"(f) : "l"(v)); return f;
}
__device__ __forceinline__ float unhi(u64 v) {
    float f; asm("{ .reg .f32 t; mov.b64 {t, %0}, %1; }" : "=f"(f) : "l"(v)); return f;
}
__device__ __forceinline__ u64 ffma2(u64 a, u64 b, u64 c) {
    u64 d; asm("fma.rn.f32x2 %0, %1, %2, %3;" : "=l"(d) : "l"(a), "l"(b), "l"(c)); return d;
}
__device__ __forceinline__ u64 fadd2(u64 a, u64 b) {
    u64 d; asm("add.rn.f32x2 %0, %1, %2;" : "=l"(d) : "l"(a), "l"(b)); return d;
}
__device__ __forceinline__ u64 shfl2(u64 v, int m) {
    unsigned lo, hi;
    asm("mov.b64 {%0,%1}, %2;" : "=r"(lo), "=r"(hi) : "l"(v));
    lo = __shfl_xor_sync(0xffffffffu, lo, m);
    hi = __shfl_xor_sync(0xffffffffu, hi, m);
    u64 r; asm("mov.b64 %0, {%1,%2};" : "=l"(r) : "r"(lo), "r"(hi)); return r;
}

union F4U2 { float4 f; u64 u[2]; };

// lanes enter with 4 u64 partials; group g=(lane>>3) exits with full sum of value g.
__device__ __forceinline__ u64 reduce4_u64(u64 a0, u64 a1, u64 a2, u64 a3, int lane)
{
    if (lane & 16) { u64 t = a0; a0 = a2; a2 = t; t = a1; a1 = a3; a3 = t; }
    a0 = fadd2(a0, shfl2(a2, 16));
    a1 = fadd2(a1, shfl2(a3, 16));
    if (lane & 8) { u64 t = a0; a0 = a1; a1 = t; }
    a0 = fadd2(a0, shfl2(a1, 8));
    a0 = fadd2(a0, shfl2(a0, 4));
    a0 = fadd2(a0, shfl2(a0, 2));
    a0 = fadd2(a0, shfl2(a0, 1));
    return a0;
}

__device__ __forceinline__ float reduce4(float a0, float a1, float a2, float a3,
                                         int lane)
{
    if (lane & 16) { float t = a0; a0 = a2; a2 = t; t = a1; a1 = a3; a3 = t; }
    a0 += __shfl_xor_sync(0xffffffffu, a2, 16);
    a1 += __shfl_xor_sync(0xffffffffu, a3, 16);
    if (lane & 8)  { float t = a0; a0 = a1; a1 = t; }
    a0 += __shfl_xor_sync(0xffffffffu, a1, 8);
    a0 += __shfl_xor_sync(0xffffffffu, a0, 4);
    a0 += __shfl_xor_sync(0xffffffffu, a0, 2);
    a0 += __shfl_xor_sync(0xffffffffu, a0, 1);
    return a0;
}

__device__ __forceinline__ float dot4(float4 a, float4 b, float acc)
{
    acc = fmaf(a.x, b.x, acc);
    acc = fmaf(a.y, b.y, acc);
    acc = fmaf(a.z, b.z, acc);
    acc = fmaf(a.w, b.w, acc);
    return acc;
}

// ============================================================================
// Kernel 1: w[b,t,:] = softmax(tanh(q@Wc^T+bc)@km^T); one warp per item PAIR.
// ============================================================================
#define K1_THREADS 256
#define K1_PAIRS   4
#define K1_GRID    ((BB * SS) / (8 * 2 * K1_PAIRS))   // 8192

__global__ __launch_bounds__(K1_THREADS)
void agm_weights_kernel(const float* __restrict__ q_emb,
                        const float* __restrict__ km,
                        const float* __restrict__ Wc,
                        const float* __restrict__ bc,
                        float* __restrict__ out)
{
    __shared__ float s_WcT[KK * KK];       // [j][k]
    __shared__ float s_kmT[KK * MM];       // [k][m]
    __shared__ float s_bc[KK];
    __shared__ float s_q [8][2][52];
    __shared__ float s_ck[8][2][52];

    const int tid  = threadIdx.x;
    const int w    = tid >> 5;
    const int lane = tid & 31;

    for (int p = tid; p < KK * KK; p += K1_THREADS) {
        int j = p / KK, k = p % KK;
        s_WcT[j * KK + k] = Wc[k * KK + j];
    }
    for (int p = tid; p < MM * KK; p += K1_THREADS) {
        int k = p / MM, m = p % MM;
        s_kmT[k * MM + m] = km[m * KK + k];
    }
    for (int p = tid; p < KK; p += K1_THREADS) s_bc[p] = bc[p];
    __syncthreads();

    const bool two = (lane < KK - 32);

    for (int it = 0; it < K1_PAIRS; ++it) {
        const int p0 = (blockIdx.x * 8 + w) * (2 * K1_PAIRS) + 2 * it;

        if (lane < 25) {
            float2 v0 = ((const float2*)(q_emb + (size_t)p0 * KK))[lane];
            float2 v1 = ((const float2*)(q_emb + (size_t)(p0 + 1) * KK))[lane];
            s_q[w][0][2 * lane] = v0.x; s_q[w][0][2 * lane + 1] = v0.y;
            s_q[w][1][2 * lane] = v1.x; s_q[w][1][2 * lane + 1] = v1.y;
        }
        __syncwarp();

        // ck for both items (shared Wc loads, 4 independent chains)
        {
            float bc1 = s_bc[lane];
            float bc2 = two ? s_bc[lane + 32] : 0.f;
            float a10 = bc1, a11 = bc1, a20 = bc2, a21 = bc2;
            #pragma unroll
            for (int j = 0; j < KK; ++j) {
                float w1 = s_WcT[j * KK + lane];
                float w2 = two ? s_WcT[j * KK + lane + 32] : 0.f;
                float q0 = s_q[w][0][j], q1 = s_q[w][1][j];
                a10 = fmaf(w1, q0, a10); a11 = fmaf(w1, q1, a11);
                a20 = fmaf(w2, q0, a20); a21 = fmaf(w2, q1, a21);
            }
            float e;
            e = __expf(2.f * a10); s_ck[w][0][lane] = 1.f - 2.f / (e + 1.f);
            e = __expf(2.f * a11); s_ck[w][1][lane] = 1.f - 2.f / (e + 1.f);
            if (two) {
                e = __expf(2.f * a20); s_ck[w][0][lane + 32] = 1.f - 2.f / (e + 1.f);
                e = __expf(2.f * a21); s_ck[w][1][lane + 32] = 1.f - 2.f / (e + 1.f);
            }
        }
        __syncwarp();

        // logits for both items + interleaved softmaxes
        float x00 = 0.f, x01 = 0.f;
        float x10 = two ? 0.f : -INFINITY;
        float x11 = two ? 0.f : -INFINITY;
        #pragma unroll
        for (int k = 0; k < KK; ++k) {
            float k1v = s_kmT[k * MM + lane];
            float k2v = two ? s_kmT[k * MM + lane + 32] : 0.f;
            float c0 = s_ck[w][0][k], c1 = s_ck[w][1][k];
            x00 = fmaf(k1v, c0, x00); x01 = fmaf(k1v, c1, x01);
            x10 = fmaf(k2v, c0, x10); x11 = fmaf(k2v, c1, x11);
        }
        if (!two) { x10 = -INFINITY; x11 = -INFINITY; }
        float mx0 = fmaxf(x00, x10), mx1 = fmaxf(x01, x11);
        #pragma unroll
        for (int o = 16; o > 0; o >>= 1) {
            mx0 = fmaxf(mx0, __shfl_xor_sync(0xffffffffu, mx0, o));
            mx1 = fmaxf(mx1, __shfl_xor_sync(0xffffffffu, mx1, o));
        }
        float e00 = __expf(x00 - mx0);
        float e10 = two ? __expf(x10 - mx0) : 0.f;
        float e01 = __expf(x01 - mx1);
        float e11 = two ? __expf(x11 - mx1) : 0.f;
        float s0 = e00 + e10, s1 = e01 + e11;
        #pragma unroll
        for (int o = 16; o > 0; o >>= 1) {
            s0 += __shfl_xor_sync(0xffffffffu, s0, o);
            s1 += __shfl_xor_sync(0xffffffffu, s1, o);
        }
        float i0 = 1.f / s0, i1 = 1.f / s1;
        out[OUT_W + (size_t)p0 * MM + lane]       = e00 * i0;
        out[OUT_W + (size_t)(p0 + 1) * MM + lane] = e01 * i1;
        if (two) {
            out[OUT_W + (size_t)p0 * MM + lane + 32]       = e10 * i0;
            out[OUT_W + (size_t)(p0 + 1) * MM + lane + 32] = e11 * i1;
        }
        __syncwarp();
    }
}

// ============================================================================
// Kernel 2: recurrence. Memory state as 25 packed f32x2 pairs per thread.
// ============================================================================

__global__ __launch_bounds__(NTHR)
void agm_recur_kernel(const float* __restrict__ att,
                      const float* __restrict__ vmem,
                      const float* __restrict__ Wr,
                      const float* __restrict__ br,
                      const float* __restrict__ We,
                      const float* __restrict__ be,
                      const float* __restrict__ Wa,
                      const float* __restrict__ ba,
                      float* __restrict__ out)
{
    extern __shared__ float sh[];

    const int tid  = threadIdx.x;
    const int lane = tid & 31;
    const int wid  = tid >> 5;
    const int gb0  = blockIdx.x * NB;

    const int bcol   = tid / VV;
    const int vcol   = tid % VV;
    const int colOff = bcol * VV + vcol;

    // ---- per-thread memory state ----
    u64 mem2[25];
    {
        const float* src = vmem + (size_t)(gb0 + bcol) * (MM * VV) + vcol;
        #pragma unroll
        for (int i = 0; i < 25; ++i)
            mem2[i] = pk2(src[(2 * i) * VV], src[(2 * i + 1) * VV]);
    }

    // ---- one-time setup ----
    for (int p = tid; p < VV * TWOA / 4; p += NTHR)
        ((float4*)(sh + OFF_WE))[p] = ((const float4*)We)[p];
    for (int p = tid; p < AA * VV; p += NTHR) {
        int a = p / VV, v = p % VV;
        sh[OFF_WR + a * 208 + v] = Wr[p];
    }
    for (int p = tid; p < AA; p += NTHR) sh[OFF_BR + p] = br[p];
    for (int p = tid; p < VV; p += NTHR) { sh[OFF_BE + p] = be[p]; sh[OFF_BA + p] = ba[p]; }
    if (tid < NB * KK) {
        int b = tid / KK, m = tid % KK;
        sh[OFF_W + b * 52 + m] = out[OUT_W + ((size_t)(gb0 + b) * SS) * MM + m];
    } else if (tid < NB * KK + NB * AA) {
        int i = tid - NB * KK;
        sh[OFF_AT + i] = att[((size_t)(gb0 + (i >> 6)) * SS) * AA + (i & 63)];
    }
    __syncthreads();

    const float beV = sh[OFF_BE + vcol];
    const float baV = sh[OFF_BA + vcol];

    // ---- hoisted prefetch pointer (each thread has ONE role) ----
    const bool isW  = (tid < NB * KK);
    const bool isAT = (!isW) && (tid < NB * KK + NB * AA);
    const float* pfPtr = 0;
    int pfStride = 0;
    if (isW) {
        pfPtr = out + OUT_W + ((size_t)(gb0 + tid / KK) * SS + 1) * MM + tid % KK;
        pfStride = MM;
    } else if (isAT) {
        int i = tid - NB * KK;
        pfPtr = att + ((size_t)(gb0 + (i >> 6)) * SS + 1) * AA + (i & 63);
        pfStride = AA;
    }
    // rc output pointer (threads < 256)
    float* rcOut = out + OUT_RC + ((size_t)(gb0 + (tid >> 6)) * SS) * AA + (tid & 63);

    // ---- hoisted G-phase lane pointers ----
    const float4* waP = (const float4*)(Wa + wid * TWOA) + lane;   // + r8*25 rows
    const float4* weP = (const float4*)(sh + OFF_WE + wid * TWOA) + lane;
    float* gdst = sh + (((lane >> 3) < 2) ? OFF_ER : OFF_AR)
                     + ((lane >> 3) & 1) * (2 * VV) + wid;

    // ---- prologue: r(0) = w(0) . mem ----
    {
        const float4* w4 = (const float4*)(sh + OFF_W) + bcol * 13;
        u64 a0 = 0, a1 = 0;
        #pragma unroll
        for (int i = 0; i < 12; ++i) {
            F4U2 ww; ww.f = w4[i];
            a0 = ffma2(ww.u[0], mem2[2 * i],     a0);
            a1 = ffma2(ww.u[1], mem2[2 * i + 1], a1);
        }
        F4U2 wl; wl.f = w4[12];
        a0 = ffma2(wl.u[0], mem2[24], a0);
        u64 s2 = fadd2(a0, a1);
        sh[OFF_R + colOff] = unlo(s2) + unhi(s2);
    }
    __syncthreads();

    for (int t = 0; t < SS; ++t) {
        const int cur = t & 1, nxt = cur ^ 1;
        const bool last = (t == SS - 1);

        // ---- prefetch issue for t+1 (guarded off on final step) ----
        float pf = 0.f;
        if (!last && (isW || isAT)) pf = *pfPtr;

        // ---- F: rc[b][a] = r[b] . Wr[a] + br[a] ----
        for (int a = wid; a < AA; a += 25) {
            const float4* wr4 = (const float4*)(sh + OFF_WR + a * 208);
            bool l2 = (lane < 18);
            float4 x = wr4[lane];
            float4 y = l2 ? wr4[32 + lane] : make_float4(0, 0, 0, 0);
            float acc[NB];
            #pragma unroll
            for (int b = 0; b < NB; ++b) {
                const float4* r4 = (const float4*)(sh + OFF_R + b * VV);
                float4 ra = r4[lane];
                float4 rb = l2 ? r4[32 + lane] : make_float4(0, 0, 0, 0);
                acc[b] = dot4(y, rb, dot4(x, ra, 0.f));
            }
            float s4 = reduce4(acc[0], acc[1], acc[2], acc[3], lane);
            if (!(lane & 7)) {
                int b = lane >> 3;
                sh[OFF_RC + b * AA + a] = s4 + sh[OFF_BR + a];
            }
        }
        __syncthreads();   // bar A

        // ---- rc out-store ----
        if (tid < NB * AA) { *rcOut = sh[OFF_RC + tid]; rcOut += AA; }
        if (last) break;

        // ---- prefetch stores (overlap with gates) ----
        if (isW) {
            sh[OFF_W + (nxt * NB + tid / KK) * 52 + tid % KK] = pf;
            pfPtr += pfStride;
        } else if (isAT) {
            sh[OFF_AT + nxt * (NB * AA) + (tid - NB * KK)] = pf;
            pfPtr += pfStride;
        }

        // ---- G: packed gate matvecs (warp-per-row; We smem + Wa gmem) ----
        {
            // load wi (att | rc) and pack batch pairs: 8 u64, register-neutral
            u64 wx01, wx23, wy01, wy23, wz01, wz23, ww01, ww23;
            {
                const float4* at4 = (const float4*)(sh + OFF_AT + cur * (NB * AA));
                const float4* rc4 = (const float4*)(sh + OFF_RC);
                int lo = lane & 15;
                float4 wi0 = (lane < 16) ? at4[0 * 16 + lo] : rc4[0 * 16 + lo];
                float4 wi1 = (lane < 16) ? at4[1 * 16 + lo] : rc4[1 * 16 + lo];
                float4 wi2 = (lane < 16) ? at4[2 * 16 + lo] : rc4[2 * 16 + lo];
                float4 wi3 = (lane < 16) ? at4[3 * 16 + lo] : rc4[3 * 16 + lo];
                wx01 = pk2(wi0.x, wi1.x); wx23 = pk2(wi2.x, wi3.x);
                wy01 = pk2(wi0.y, wi1.y); wy23 = pk2(wi2.y, wi3.y);
                wz01 = pk2(wi0.z, wi1.z); wz23 = pk2(wi2.z, wi3.z);
                ww01 = pk2(wi0.w, wi1.w); ww23 = pk2(wi2.w, wi3.w);
            }
            #pragma unroll
            for (int r8 = 0; r8 < 8; ++r8) {
                float4 wa = waP[r8 * 25 * (TWOA / 4)];   // LDG early, imm offset
                float4 we = weP[r8 * 25 * (TWOA / 4)];
                u64 E01 = 0, E23 = 0, A01 = 0, A23 = 0;
                u64 b2;
                b2 = pk2(we.x, we.x); E01 = ffma2(b2, wx01, E01); E23 = ffma2(b2, wx23, E23);
                b2 = pk2(we.y, we.y); E01 = ffma2(b2, wy01, E01); E23 = ffma2(b2, wy23, E23);
                b2 = pk2(we.z, we.z); E01 = ffma2(b2, wz01, E01); E23 = ffma2(b2, wz23, E23);
                b2 = pk2(we.w, we.w); E01 = ffma2(b2, ww01, E01); E23 = ffma2(b2, ww23, E23);
                b2 = pk2(wa.x, wa.x); A01 = ffma2(b2, wx01, A01); A23 = ffma2(b2, wx23, A23);
                b2 = pk2(wa.y, wa.y); A01 = ffma2(b2, wy01, A01); A23 = ffma2(b2, wy23, A23);
                b2 = pk2(wa.z, wa.z); A01 = ffma2(b2, wz01, A01); A23 = ffma2(b2, wz23, A23);
                b2 = pk2(wa.w, wa.w); A01 = ffma2(b2, ww01, A01); A23 = ffma2(b2, ww23, A23);
                u64 s2 = reduce4_u64(E01, E23, A01, A23, lane);
                if (!(lane & 7)) {
                    gdst[25 * r8]      = unlo(s2);
                    gdst[VV + 25 * r8] = unhi(s2);
                }
            }
        }
        __syncthreads();   // bar B

        // ---- fused H+E (packed): update with w(t), read with w(t+1) ----
        {
            float re = sh[OFF_ER + colOff] + beV;
            float ra = sh[OFF_AR + colOff] + baV;
            float er = 1.f / (1.f + __expf(-re));
            float ea = __expf(2.f * ra);
            float ad = 1.f - 2.f / (ea + 1.f);

            u64 nEr2 = pk2(-er, -er);
            u64 ad2  = pk2(ad, ad);

            const float4* wc4 = (const float4*)(sh + OFF_W) + (cur * NB + bcol) * 13;
            const float4* wn4 = (const float4*)(sh + OFF_W) + (nxt * NB + bcol) * 13;
            u64 a0 = 0, a1 = 0;
            #pragma unroll
            for (int i = 0; i < 12; ++i) {
                F4U2 wc; wc.f = wc4[i];
                F4U2 wn; wn.f = wn4[i];
                u64 m0 = mem2[2 * i];
                u64 m1 = mem2[2 * i + 1];
                m0 = ffma2(wc.u[0], ffma2(nEr2, m0, ad2), m0);
                m1 = ffma2(wc.u[1], ffma2(nEr2, m1, ad2), m1);
                a0 = ffma2(wn.u[0], m0, a0);
                a1 = ffma2(wn.u[1], m1, a1);
                mem2[2 * i]     = m0;
                mem2[2 * i + 1] = m1;
            }
            F4U2 wcl; wcl.f = wc4[12];
            F4U2 wnl; wnl.f = wn4[12];
            u64 m = mem2[24];
            m = ffma2(wcl.u[0], ffma2(nEr2, m, ad2), m);
            a0 = ffma2(wnl.u[0], m, a0);
            mem2[24] = m;
            u64 s2 = fadd2(a0, a1);
            sh[OFF_R + colOff] = unlo(s2) + unhi(s2);
        }
        __syncthreads();   // bar C
    }

    // ---- final memory state ----
    {
        float* dst = out + OUT_MEM + (size_t)(gb0 + bcol) * (MM * VV) + vcol;
        #pragma unroll
        for (int i = 0; i < 25; ++i) {
            dst[(2 * i) * VV]     = unlo(mem2[i]);
            dst[(2 * i + 1) * VV] = unhi(mem2[i]);
        }
    }
}

extern "C" void kernel_launch(void* const* d_in, const int* in_sizes, int n_in,
                              void* d_out, int out_size)
{
    (void)in_sizes; (void)n_in; (void)out_size;
    const float* q_emb = (const float*)d_in[0];
    const float* att   = (const float*)d_in[1];
    const float* vmem  = (const float*)d_in[2];
    const float* km    = (const float*)d_in[3];
    const float* Wc    = (const float*)d_in[4];
    const float* bc    = (const float*)d_in[5];
    const float* Wr    = (const float*)d_in[6];
    const float* br    = (const float*)d_in[7];
    const float* We    = (const float*)d_in[8];
    const float* be    = (const float*)d_in[9];
    const float* Wa    = (const float*)d_in[10];
    const float* ba    = (const float*)d_in[11];
    float* out = (float*)d_out;

    cudaFuncSetAttribute(agm_recur_kernel,
                         cudaFuncAttributeMaxDynamicSharedMemorySize,
                         SMEM2_BYTES);

    agm_weights_kernel<<<K1_GRID, K1_THREADS>>>(q_emb, km, Wc, bc, out);
    agm_recur_kernel<<<NBLK, NTHR, SMEM2_BYTES>>>(att, vmem, Wr, br,
                                                  We, be, Wa, ba, out);
}

// round 11
// speedup vs baseline: 1.0573x; 1.0573x over previous
#include <cuda_runtime.h>
#include <math.h>

#define BB   512
#define SS   1024
#define KK   50
#define MM   50
#define VV   200
#define AA   64
#define TWOA 128
#define NB   4
#define NBLK (BB / NB)     // 128 CTAs
#define NTHR 800           // 25 warps

// ---- kernel2 dynamic shared layout (float offsets, all 16B aligned) ----
#define OFF_WE  0                        // 25600 (We rows)
#define OFF_WR  (OFF_WE + VV*TWOA)       // 13312 (Wr rows padded to 208)
#define OFF_W   (OFF_WR + AA*208)        // 2*4*52 double-buffered w
#define OFF_AT  (OFF_W  + 2*NB*52)       // 2*256 double-buffered att
#define OFF_RC  (OFF_AT + 2*NB*AA)       // 256
#define OFF_R   (OFF_RC + NB*AA)         // 800
#define OFF_ER  (OFF_R  + NB*VV)         // 800
#define OFF_AR  (OFF_ER + NB*VV)         // 800
#define OFF_BR  (OFF_AR + NB*VV)         // 64
#define OFF_BE  (OFF_BR + AA)            // 200
#define OFF_BA  (OFF_BE + VV)            // 200
#define SMEM2_FLOATS (OFF_BA + VV)
#define SMEM2_BYTES  (SMEM2_FLOATS * 4)  // ~171.8 KB

// Output offsets (floats) in concatenated flat output
#define OUT_RC  0ULL                                        // (B,S,A)
#define OUT_MEM ((unsigned long long)BB * SS * AA)          // (B,M,V)
#define OUT_W   (OUT_MEM + (unsigned long long)BB*MM*VV)    // (B,S,M)

// ---- packed f32x2 helpers (used only where data LIVES packed: mem2) ----
typedef unsigned long long u64;

__device__ __forceinline__ u64 pk2(float lo, float hi) {
    u64 d; asm("mov.b64 %0, {%1, %2};" : "=l"(d) : "f"(lo), "f"(hi)); return d;
}
__device__ __forceinline__ float unlo(u64 v) {
    float f; asm("{ .reg .f32 t; mov.b64 {%0, t}, %1; }" : "=f"(f) : "l"(v)); return f;
}
__device__ __forceinline__ float unhi(u64 v) {
    float f; asm("{ .reg .f32 t; mov.b64 {t, %0}, %1; }" : "=f"(f) : "l"(v)); return f;
}
__device__ __forceinline__ u64 ffma2(u64 a, u64 b, u64 c) {
    u64 d; asm("fma.rn.f32x2 %0, %1, %2, %3;" : "=l"(d) : "l"(a), "l"(b), "l"(c)); return d;
}
__device__ __forceinline__ u64 fadd2(u64 a, u64 b) {
    u64 d; asm("add.rn.f32x2 %0, %1, %2;" : "=l"(d) : "l"(a), "l"(b)); return d;
}

union F4U2 { float4 f; u64 u[2]; };

__device__ __forceinline__ float reduce4(float a0, float a1, float a2, float a3,
                                         int lane)
{
    if (lane & 16) { float t = a0; a0 = a2; a2 = t; t = a1; a1 = a3; a3 = t; }
    a0 += __shfl_xor_sync(0xffffffffu, a2, 16);
    a1 += __shfl_xor_sync(0xffffffffu, a3, 16);
    if (lane & 8)  { float t = a0; a0 = a1; a1 = t; }
    a0 += __shfl_xor_sync(0xffffffffu, a1, 8);
    a0 += __shfl_xor_sync(0xffffffffu, a0, 4);
    a0 += __shfl_xor_sync(0xffffffffu, a0, 2);
    a0 += __shfl_xor_sync(0xffffffffu, a0, 1);
    return a0;
}

__device__ __forceinline__ float dot4(float4 a, float4 b, float acc)
{
    acc = fmaf(a.x, b.x, acc);
    acc = fmaf(a.y, b.y, acc);
    acc = fmaf(a.z, b.z, acc);
    acc = fmaf(a.w, b.w, acc);
    return acc;
}

// ============================================================================
// Kernel 1: w[b,t,:] = softmax(tanh(q@Wc^T+bc)@km^T); one warp per item PAIR
// (shared LDS across the pair -> 2x fma:LDS ratio, 4 independent chains).
// ============================================================================
#define K1_THREADS 256
#define K1_PAIRS   4
#define K1_GRID    ((BB * SS) / (8 * 2 * K1_PAIRS))   // 8192

__global__ __launch_bounds__(K1_THREADS)
void agm_weights_kernel(const float* __restrict__ q_emb,
                        const float* __restrict__ km,
                        const float* __restrict__ Wc,
                        const float* __restrict__ bc,
                        float* __restrict__ out)
{
    __shared__ float s_WcT[KK * KK];       // [j][k]
    __shared__ float s_kmT[KK * MM];       // [k][m]
    __shared__ float s_bc[KK];
    __shared__ float s_q [8][2][52];
    __shared__ float s_ck[8][2][52];

    const int tid  = threadIdx.x;
    const int w    = tid >> 5;
    const int lane = tid & 31;

    for (int p = tid; p < KK * KK; p += K1_THREADS) {
        int j = p / KK, k = p % KK;
        s_WcT[j * KK + k] = Wc[k * KK + j];
    }
    for (int p = tid; p < MM * KK; p += K1_THREADS) {
        int k = p / MM, m = p % MM;
        s_kmT[k * MM + m] = km[m * KK + k];
    }
    for (int p = tid; p < KK; p += K1_THREADS) s_bc[p] = bc[p];
    __syncthreads();

    const bool two = (lane < KK - 32);

    for (int it = 0; it < K1_PAIRS; ++it) {
        const int p0 = (blockIdx.x * 8 + w) * (2 * K1_PAIRS) + 2 * it;

        if (lane < 25) {
            float2 v0 = ((const float2*)(q_emb + (size_t)p0 * KK))[lane];
            float2 v1 = ((const float2*)(q_emb + (size_t)(p0 + 1) * KK))[lane];
            s_q[w][0][2 * lane] = v0.x; s_q[w][0][2 * lane + 1] = v0.y;
            s_q[w][1][2 * lane] = v1.x; s_q[w][1][2 * lane + 1] = v1.y;
        }
        __syncwarp();

        {
            float bc1 = s_bc[lane];
            float bc2 = two ? s_bc[lane + 32] : 0.f;
            float a10 = bc1, a11 = bc1, a20 = bc2, a21 = bc2;
            #pragma unroll
            for (int j = 0; j < KK; ++j) {
                float w1 = s_WcT[j * KK + lane];
                float w2 = two ? s_WcT[j * KK + lane + 32] : 0.f;
                float q0 = s_q[w][0][j], q1 = s_q[w][1][j];
                a10 = fmaf(w1, q0, a10); a11 = fmaf(w1, q1, a11);
                a20 = fmaf(w2, q0, a20); a21 = fmaf(w2, q1, a21);
            }
            float e;
            e = __expf(2.f * a10); s_ck[w][0][lane] = 1.f - 2.f / (e + 1.f);
            e = __expf(2.f * a11); s_ck[w][1][lane] = 1.f - 2.f / (e + 1.f);
            if (two) {
                e = __expf(2.f * a20); s_ck[w][0][lane + 32] = 1.f - 2.f / (e + 1.f);
                e = __expf(2.f * a21); s_ck[w][1][lane + 32] = 1.f - 2.f / (e + 1.f);
            }
        }
        __syncwarp();

        float x00 = 0.f, x01 = 0.f;
        float x10 = 0.f, x11 = 0.f;
        #pragma unroll
        for (int k = 0; k < KK; ++k) {
            float k1v = s_kmT[k * MM + lane];
            float k2v = two ? s_kmT[k * MM + lane + 32] : 0.f;
            float c0 = s_ck[w][0][k], c1 = s_ck[w][1][k];
            x00 = fmaf(k1v, c0, x00); x01 = fmaf(k1v, c1, x01);
            x10 = fmaf(k2v, c0, x10); x11 = fmaf(k2v, c1, x11);
        }
        if (!two) { x10 = -INFINITY; x11 = -INFINITY; }
        float mx0 = fmaxf(x00, x10), mx1 = fmaxf(x01, x11);
        #pragma unroll
        for (int o = 16; o > 0; o >>= 1) {
            mx0 = fmaxf(mx0, __shfl_xor_sync(0xffffffffu, mx0, o));
            mx1 = fmaxf(mx1, __shfl_xor_sync(0xffffffffu, mx1, o));
        }
        float e00 = __expf(x00 - mx0);
        float e10 = two ? __expf(x10 - mx0) : 0.f;
        float e01 = __expf(x01 - mx1);
        float e11 = two ? __expf(x11 - mx1) : 0.f;
        float s0 = e00 + e10, s1 = e01 + e11;
        #pragma unroll
        for (int o = 16; o > 0; o >>= 1) {
            s0 += __shfl_xor_sync(0xffffffffu, s0, o);
            s1 += __shfl_xor_sync(0xffffffffu, s1, o);
        }
        float i0 = 1.f / s0, i1 = 1.f / s1;
        out[OUT_W + (size_t)p0 * MM + lane]       = e00 * i0;
        out[OUT_W + (size_t)(p0 + 1) * MM + lane] = e01 * i1;
        if (two) {
            out[OUT_W + (size_t)p0 * MM + lane + 32]       = e10 * i0;
            out[OUT_W + (size_t)(p0 + 1) * MM + lane + 32] = e11 * i1;
        }
        __syncwarp();
    }
}

// ============================================================================
// Kernel 2: recurrence. Memory state as 25 packed f32x2 pairs per thread.
// G phase: SCALAR merged We+Wa (the R9 winner). Light pointer hoists only.
// ============================================================================

__global__ __launch_bounds__(NTHR)
void agm_recur_kernel(const float* __restrict__ att,
                      const float* __restrict__ vmem,
                      const float* __restrict__ Wr,
                      const float* __restrict__ br,
                      const float* __restrict__ We,
                      const float* __restrict__ be,
                      const float* __restrict__ Wa,
                      const float* __restrict__ ba,
                      float* __restrict__ out)
{
    extern __shared__ float sh[];

    const int tid  = threadIdx.x;
    const int lane = tid & 31;
    const int wid  = tid >> 5;
    const int gb0  = blockIdx.x * NB;

    const int bcol   = tid / VV;
    const int vcol   = tid % VV;
    const int colOff = bcol * VV + vcol;

    // ---- per-thread memory state ----
    u64 mem2[25];
    {
        const float* src = vmem + (size_t)(gb0 + bcol) * (MM * VV) + vcol;
        #pragma unroll
        for (int i = 0; i < 25; ++i)
            mem2[i] = pk2(src[(2 * i) * VV], src[(2 * i + 1) * VV]);
    }

    // ---- one-time setup ----
    for (int p = tid; p < VV * TWOA / 4; p += NTHR)
        ((float4*)(sh + OFF_WE))[p] = ((const float4*)We)[p];
    for (int p = tid; p < AA * VV; p += NTHR) {
        int a = p / VV, v = p % VV;
        sh[OFF_WR + a * 208 + v] = Wr[p];
    }
    for (int p = tid; p < AA; p += NTHR) sh[OFF_BR + p] = br[p];
    for (int p = tid; p < VV; p += NTHR) { sh[OFF_BE + p] = be[p]; sh[OFF_BA + p] = ba[p]; }
    if (tid < NB * KK) {
        int b = tid / KK, m = tid % KK;
        sh[OFF_W + b * 52 + m] = out[OUT_W + ((size_t)(gb0 + b) * SS) * MM + m];
    } else if (tid < NB * KK + NB * AA) {
        int i = tid - NB * KK;
        sh[OFF_AT + i] = att[((size_t)(gb0 + (i >> 6)) * SS) * AA + (i & 63)];
    }
    __syncthreads();

    const float beV = sh[OFF_BE + vcol];
    const float baV = sh[OFF_BA + vcol];

    // ---- hoisted prefetch / output pointers ----
    const bool isW  = (tid < NB * KK);
    const bool isAT = (!isW) && (tid < NB * KK + NB * AA);
    const float* pfPtr = 0;
    int pfStride = 0;
    if (isW) {
        pfPtr = out + OUT_W + ((size_t)(gb0 + tid / KK) * SS + 1) * MM + tid % KK;
        pfStride = MM;
    } else if (isAT) {
        int i = tid - NB * KK;
        pfPtr = att + ((size_t)(gb0 + (i >> 6)) * SS + 1) * AA + (i & 63);
        pfStride = AA;
    }
    float* rcOut = out + OUT_RC + ((size_t)(gb0 + (tid >> 6)) * SS) * AA + (tid & 63);

    // ---- prologue: r(0) = w(0) . mem ----
    {
        const float4* w4 = (const float4*)(sh + OFF_W) + bcol * 13;
        u64 a0 = 0, a1 = 0;
        #pragma unroll
        for (int i = 0; i < 12; ++i) {
            F4U2 ww; ww.f = w4[i];
            a0 = ffma2(ww.u[0], mem2[2 * i],     a0);
            a1 = ffma2(ww.u[1], mem2[2 * i + 1], a1);
        }
        F4U2 wl; wl.f = w4[12];
        a0 = ffma2(wl.u[0], mem2[24], a0);
        u64 s2 = fadd2(a0, a1);
        sh[OFF_R + colOff] = unlo(s2) + unhi(s2);
    }
    __syncthreads();

    for (int t = 0; t < SS; ++t) {
        const int cur = t & 1, nxt = cur ^ 1;
        const bool last = (t == SS - 1);

        // ---- prefetch issue for t+1 ----
        float pf = 0.f;
        if (!last && (isW || isAT)) pf = *pfPtr;

        // ---- F: rc[b][a] = r[b] . Wr[a] + br[a] ----
        for (int a = wid; a < AA; a += 25) {
            const float4* wr4 = (const float4*)(sh + OFF_WR + a * 208);
            bool l2 = (lane < 18);
            float4 x = wr4[lane];
            float4 y = l2 ? wr4[32 + lane] : make_float4(0, 0, 0, 0);
            float acc[NB];
            #pragma unroll
            for (int b = 0; b < NB; ++b) {
                const float4* r4 = (const float4*)(sh + OFF_R + b * VV);
                float4 ra = r4[lane];
                float4 rb = l2 ? r4[32 + lane] : make_float4(0, 0, 0, 0);
                acc[b] = dot4(y, rb, dot4(x, ra, 0.f));
            }
            float s4 = reduce4(acc[0], acc[1], acc[2], acc[3], lane);
            if (!(lane & 7)) {
                int b = lane >> 3;
                sh[OFF_RC + b * AA + a] = s4 + sh[OFF_BR + a];
            }
        }
        __syncthreads();   // bar A

        // ---- rc out-store ----
        if (tid < NB * AA) { *rcOut = sh[OFF_RC + tid]; rcOut += AA; }
        if (last) break;

        // ---- prefetch stores (overlap with gates) ----
        if (isW) {
            sh[OFF_W + (nxt * NB + tid / KK) * 52 + tid % KK] = pf;
            pfPtr += pfStride;
        } else if (isAT) {
            sh[OFF_AT + nxt * (NB * AA) + (tid - NB * KK)] = pf;
            pfPtr += pfStride;
        }

        // ---- G: merged gate matvecs (SCALAR; warp-per-row, We smem + Wa gmem) ----
        {
            float4 wi0, wi1, wi2, wi3;
            {
                const float4* at4 = (const float4*)(sh + OFF_AT + cur * (NB * AA));
                const float4* rc4 = (const float4*)(sh + OFF_RC);
                int lo = lane & 15;
                wi0 = (lane < 16) ? at4[0 * 16 + lo] : rc4[0 * 16 + lo];
                wi1 = (lane < 16) ? at4[1 * 16 + lo] : rc4[1 * 16 + lo];
                wi2 = (lane < 16) ? at4[2 * 16 + lo] : rc4[2 * 16 + lo];
                wi3 = (lane < 16) ? at4[3 * 16 + lo] : rc4[3 * 16 + lo];
            }
            #pragma unroll 4
            for (int r8 = 0; r8 < 8; ++r8) {
                int v = wid + 25 * r8;
                float4 wa = ((const float4*)(Wa + v * TWOA))[lane];   // LDG early
                float4 we = ((const float4*)(sh + OFF_WE + v * TWOA))[lane];
                float e0 = dot4(we, wi0, 0.f);
                float e1 = dot4(we, wi1, 0.f);
                float e2 = dot4(we, wi2, 0.f);
                float e3 = dot4(we, wi3, 0.f);
                float g0 = dot4(wa, wi0, 0.f);
                float g1 = dot4(wa, wi1, 0.f);
                float g2 = dot4(wa, wi2, 0.f);
                float g3 = dot4(wa, wi3, 0.f);
                float se = reduce4(e0, e1, e2, e3, lane);
                float sg = reduce4(g0, g1, g2, g3, lane);
                if (!(lane & 7)) {
                    sh[OFF_ER + (lane >> 3) * VV + v] = se;
                    sh[OFF_AR + (lane >> 3) * VV + v] = sg;
                }
            }
        }
        __syncthreads();   // bar B

        // ---- fused H+E (packed f32x2): update with w(t), read with w(t+1) ----
        {
            float re = sh[OFF_ER + colOff] + beV;
            float ra = sh[OFF_AR + colOff] + baV;
            float er = 1.f / (1.f + __expf(-re));          // sigmoid
            float ea = __expf(2.f * ra);
            float ad = 1.f - 2.f / (ea + 1.f);             // tanh

            u64 nEr2 = pk2(-er, -er);
            u64 ad2  = pk2(ad, ad);

            const float4* wc4 = (const float4*)(sh + OFF_W) + (cur * NB + bcol) * 13;
            const float4* wn4 = (const float4*)(sh + OFF_W) + (nxt * NB + bcol) * 13;
            u64 a0 = 0, a1 = 0;
            #pragma unroll
            for (int i = 0; i < 12; ++i) {
                F4U2 wc; wc.f = wc4[i];
                F4U2 wn; wn.f = wn4[i];
                u64 m0 = mem2[2 * i];
                u64 m1 = mem2[2 * i + 1];
                m0 = ffma2(wc.u[0], ffma2(nEr2, m0, ad2), m0);
                m1 = ffma2(wc.u[1], ffma2(nEr2, m1, ad2), m1);
                a0 = ffma2(wn.u[0], m0, a0);
                a1 = ffma2(wn.u[1], m1, a1);
                mem2[2 * i]     = m0;
                mem2[2 * i + 1] = m1;
            }
            F4U2 wcl; wcl.f = wc4[12];
            F4U2 wnl; wnl.f = wn4[12];
            u64 m = mem2[24];
            m = ffma2(wcl.u[0], ffma2(nEr2, m, ad2), m);
            a0 = ffma2(wnl.u[0], m, a0);
            mem2[24] = m;
            u64 s2 = fadd2(a0, a1);
            sh[OFF_R + colOff] = unlo(s2) + unhi(s2);
        }
        __syncthreads();   // bar C
    }

    // ---- final memory state ----
    {
        float* dst = out + OUT_MEM + (size_t)(gb0 + bcol) * (MM * VV) + vcol;
        #pragma unroll
        for (int i = 0; i < 25; ++i) {
            dst[(2 * i) * VV]     = unlo(mem2[i]);
            dst[(2 * i + 1) * VV] = unhi(mem2[i]);
        }
    }
}

extern "C" void kernel_launch(void* const* d_in, const int* in_sizes, int n_in,
                              void* d_out, int out_size)
{
    (void)in_sizes; (void)n_in; (void)out_size;
    const float* q_emb = (const float*)d_in[0];
    const float* att   = (const float*)d_in[1];
    const float* vmem  = (const float*)d_in[2];
    const float* km    = (const float*)d_in[3];
    const float* Wc    = (const float*)d_in[4];
    const float* bc    = (const float*)d_in[5];
    const float* Wr    = (const float*)d_in[6];
    const float* br    = (const float*)d_in[7];
    const float* We    = (const float*)d_in[8];
    const float* be    = (const float*)d_in[9];
    const float* Wa    = (const float*)d_in[10];
    const float* ba    = (const float*)d_in[11];
    float* out = (float*)d_out;

    cudaFuncSetAttribute(agm_recur_kernel,
                         cudaFuncAttributeMaxDynamicSharedMemorySize,
                         SMEM2_BYTES);

    agm_weights_kernel<<<K1_GRID, K1_THREADS>>>(q_emb, km, Wc, bc, out);
    agm_recur_kernel<<<NBLK, NTHR, SMEM2_BYTES>>>(att, vmem, Wr, br,
                                                  We, be, Wa, ba, out);
}

// round 13
// speedup vs baseline: 1.1744x; 1.1108x over previous
#include <cuda_runtime.h>
#include <math.h>

#define BB   512
#define SS   1024
#define KK   50
#define MM   50
#define VV   200
#define AA   64
#define TWOA 128
#define NB   4
#define NBLK (BB / NB)     // 128 CTAs
#define NTHR 800           // 25 warps
#define RCS  68            // rc row stride (floats)

// ---- kernel2 dynamic shared layout (float offsets, all 16B aligned) ----
#define OFF_WE  0                        // 25600
#define OFF_WR  (OFF_WE + VV*TWOA)       // 13312 (Wr rows padded to 208)
#define OFF_W   (OFF_WR + AA*208)        // 416
#define OFF_AT  (OFF_W  + 2*NB*52)       // 512
#define OFF_RC  (OFF_AT + 2*NB*AA)       // 4*68 = 272
#define OFF_R   (OFF_RC + NB*RCS)        // 800
#define OFF_ER  (OFF_R  + NB*VV)         // 800
#define OFF_AR  (OFF_ER + NB*VV + 4)     // 800 (+4: disjoint banks vs ER)
#define OFF_BR  (OFF_AR + NB*VV)         // 64
#define OFF_BE  (OFF_BR + AA)            // 200
#define OFF_BA  (OFF_BE + VV)            // 200
#define SMEM2_FLOATS (OFF_BA + VV)
#define SMEM2_BYTES  (SMEM2_FLOATS * 4)

// Output offsets (floats) in concatenated flat output
#define OUT_RC  0ULL                                        // (B,S,A)
#define OUT_MEM ((unsigned long long)BB * SS * AA)          // (B,M,V)
#define OUT_W   (OUT_MEM + (unsigned long long)BB*MM*VV)    // (B,S,M)

// ---- packed f32x2 helpers (only where data LIVES packed: mem2) ----
typedef unsigned long long u64;

__device__ __forceinline__ u64 pk2(float lo, float hi) {
    u64 d; asm("mov.b64 %0, {%1, %2};" : "=l"(d) : "f"(lo), "f"(hi)); return d;
}
__device__ __forceinline__ float unlo(u64 v) {
    float f; asm("{ .reg .f32 t; mov.b64 {%0, t}, %1; }" : "=f"(f) : "l"(v)); return f;
}
__device__ __forceinline__ float unhi(u64 v) {
    float f; asm("{ .reg .f32 t; mov.b64 {t, %0}, %1; }" : "=f"(f) : "l"(v)); return f;
}
__device__ __forceinline__ u64 ffma2(u64 a, u64 b, u64 c) {
    u64 d; asm("fma.rn.f32x2 %0, %1, %2, %3;" : "=l"(d) : "l"(a), "l"(b), "l"(c)); return d;
}
__device__ __forceinline__ u64 fadd2(u64 a, u64 b) {
    u64 d; asm("add.rn.f32x2 %0, %1, %2;" : "=l"(d) : "l"(a), "l"(b)); return d;
}

union F4U2 { float4 f; u64 u[2]; };

// 8-value butterfly: every lane exits with the full sum of value (lane>>2)
// for lanes where (lane&3)==0 (general mapping: bit4*4 + bit3*2 + bit2).
__device__ __forceinline__ float reduce8(float v0, float v1, float v2, float v3,
                                         float v4, float v5, float v6, float v7,
                                         int lane)
{
    if (lane & 16) { float t;
        t=v0;v0=v4;v4=t; t=v1;v1=v5;v5=t; t=v2;v2=v6;v6=t; t=v3;v3=v7;v7=t; }
    v0 += __shfl_xor_sync(0xffffffffu, v4, 16);
    v1 += __shfl_xor_sync(0xffffffffu, v5, 16);
    v2 += __shfl_xor_sync(0xffffffffu, v6, 16);
    v3 += __shfl_xor_sync(0xffffffffu, v7, 16);
    if (lane & 8) { float t; t=v0;v0=v2;v2=t; t=v1;v1=v3;v3=t; }
    v0 += __shfl_xor_sync(0xffffffffu, v2, 8);
    v1 += __shfl_xor_sync(0xffffffffu, v3, 8);
    if (lane & 4) { float t=v0; v0=v1; v1=t; }
    v0 += __shfl_xor_sync(0xffffffffu, v1, 4);
    v0 += __shfl_xor_sync(0xffffffffu, v0, 2);
    v0 += __shfl_xor_sync(0xffffffffu, v0, 1);
    return v0;
}

__device__ __forceinline__ float reduce4(float a0, float a1, float a2, float a3,
                                         int lane)
{
    if (lane & 16) { float t = a0; a0 = a2; a2 = t; t = a1; a1 = a3; a3 = t; }
    a0 += __shfl_xor_sync(0xffffffffu, a2, 16);
    a1 += __shfl_xor_sync(0xffffffffu, a3, 16);
    if (lane & 8)  { float t = a0; a0 = a1; a1 = t; }
    a0 += __shfl_xor_sync(0xffffffffu, a1, 8);
    a0 += __shfl_xor_sync(0xffffffffu, a0, 4);
    a0 += __shfl_xor_sync(0xffffffffu, a0, 2);
    a0 += __shfl_xor_sync(0xffffffffu, a0, 1);
    return a0;
}

__device__ __forceinline__ float dot4(float4 a, float4 b, float acc)
{
    acc = fmaf(a.x, b.x, acc);
    acc = fmaf(a.y, b.y, acc);
    acc = fmaf(a.z, b.z, acc);
    acc = fmaf(a.w, b.w, acc);
    return acc;
}

// ============================================================================
// Kernel 1: w[b,t,:] = softmax(tanh(q@Wc^T+bc)@km^T); one warp per item PAIR.
// ============================================================================
#define K1_THREADS 256
#define K1_PAIRS   4
#define K1_GRID    ((BB * SS) / (8 * 2 * K1_PAIRS))   // 8192

__global__ __launch_bounds__(K1_THREADS)
void agm_weights_kernel(const float* __restrict__ q_emb,
                        const float* __restrict__ km,
                        const float* __restrict__ Wc,
                        const float* __restrict__ bc,
                        float* __restrict__ out)
{
    __shared__ float s_WcT[KK * KK];       // [j][k]
    __shared__ float s_kmT[KK * MM];       // [k][m]
    __shared__ float s_bc[KK];
    __shared__ float s_q [8][2][52];
    __shared__ float s_ck[8][2][52];

    const int tid  = threadIdx.x;
    const int w    = tid >> 5;
    const int lane = tid & 31;

    for (int p = tid; p < KK * KK; p += K1_THREADS) {
        int j = p / KK, k = p % KK;
        s_WcT[j * KK + k] = Wc[k * KK + j];
    }
    for (int p = tid; p < MM * KK; p += K1_THREADS) {
        int k = p / MM, m = p % MM;
        s_kmT[k * MM + m] = km[m * KK + k];
    }
    for (int p = tid; p < KK; p += K1_THREADS) s_bc[p] = bc[p];
    __syncthreads();

    const bool two = (lane < KK - 32);

    for (int it = 0; it < K1_PAIRS; ++it) {
        const int p0 = (blockIdx.x * 8 + w) * (2 * K1_PAIRS) + 2 * it;

        if (lane < 25) {
            float2 v0 = ((const float2*)(q_emb + (size_t)p0 * KK))[lane];
            float2 v1 = ((const float2*)(q_emb + (size_t)(p0 + 1) * KK))[lane];
            s_q[w][0][2 * lane] = v0.x; s_q[w][0][2 * lane + 1] = v0.y;
            s_q[w][1][2 * lane] = v1.x; s_q[w][1][2 * lane + 1] = v1.y;
        }
        __syncwarp();

        {
            float bc1 = s_bc[lane];
            float bc2 = two ? s_bc[lane + 32] : 0.f;
            float a10 = bc1, a11 = bc1, a20 = bc2, a21 = bc2;
            #pragma unroll
            for (int j = 0; j < KK; ++j) {
                float w1 = s_WcT[j * KK + lane];
                float w2 = two ? s_WcT[j * KK + lane + 32] : 0.f;
                float q0 = s_q[w][0][j], q1 = s_q[w][1][j];
                a10 = fmaf(w1, q0, a10); a11 = fmaf(w1, q1, a11);
                a20 = fmaf(w2, q0, a20); a21 = fmaf(w2, q1, a21);
            }
            float e;
            e = __expf(2.f * a10); s_ck[w][0][lane] = 1.f - 2.f / (e + 1.f);
            e = __expf(2.f * a11); s_ck[w][1][lane] = 1.f - 2.f / (e + 1.f);
            if (two) {
                e = __expf(2.f * a20); s_ck[w][0][lane + 32] = 1.f - 2.f / (e + 1.f);
                e = __expf(2.f * a21); s_ck[w][1][lane + 32] = 1.f - 2.f / (e + 1.f);
            }
        }
        __syncwarp();

        float x00 = 0.f, x01 = 0.f;
        float x10 = 0.f, x11 = 0.f;
        #pragma unroll
        for (int k = 0; k < KK; ++k) {
            float k1v = s_kmT[k * MM + lane];
            float k2v = two ? s_kmT[k * MM + lane + 32] : 0.f;
            float c0 = s_ck[w][0][k], c1 = s_ck[w][1][k];
            x00 = fmaf(k1v, c0, x00); x01 = fmaf(k1v, c1, x01);
            x10 = fmaf(k2v, c0, x10); x11 = fmaf(k2v, c1, x11);
        }
        if (!two) { x10 = -INFINITY; x11 = -INFINITY; }
        float mx0 = fmaxf(x00, x10), mx1 = fmaxf(x01, x11);
        #pragma unroll
        for (int o = 16; o > 0; o >>= 1) {
            mx0 = fmaxf(mx0, __shfl_xor_sync(0xffffffffu, mx0, o));
            mx1 = fmaxf(mx1, __shfl_xor_sync(0xffffffffu, mx1, o));
        }
        float e00 = __expf(x00 - mx0);
        float e10 = two ? __expf(x10 - mx0) : 0.f;
        float e01 = __expf(x01 - mx1);
        float e11 = two ? __expf(x11 - mx1) : 0.f;
        float s0 = e00 + e10, s1 = e01 + e11;
        #pragma unroll
        for (int o = 16; o > 0; o >>= 1) {
            s0 += __shfl_xor_sync(0xffffffffu, s0, o);
            s1 += __shfl_xor_sync(0xffffffffu, s1, o);
        }
        float i0 = 1.f / s0, i1 = 1.f / s1;
        out[OUT_W + (size_t)p0 * MM + lane]       = e00 * i0;
        out[OUT_W + (size_t)(p0 + 1) * MM + lane] = e01 * i1;
        if (two) {
            out[OUT_W + (size_t)p0 * MM + lane + 32]       = e10 * i0;
            out[OUT_W + (size_t)(p0 + 1) * MM + lane + 32] = e11 * i1;
        }
        __syncwarp();
    }
}

// ============================================================================
// Kernel 2: recurrence. mem state packed f32x2; F row-pairs; reduce8.
// ============================================================================

__global__ __launch_bounds__(NTHR)
void agm_recur_kernel(const float* __restrict__ att,
                      const float* __restrict__ vmem,
                      const float* __restrict__ Wr,
                      const float* __restrict__ br,
                      const float* __restrict__ We,
                      const float* __restrict__ be,
                      const float* __restrict__ Wa,
                      const float* __restrict__ ba,
                      float* __restrict__ out)
{
    extern __shared__ float sh[];

    const int tid  = threadIdx.x;
    const int lane = tid & 31;
    const int wid  = tid >> 5;
    const int gb0  = blockIdx.x * NB;

    const int bcol   = tid / VV;
    const int vcol   = tid % VV;
    const int colOff = bcol * VV + vcol;

    // ---- per-thread memory state ----
    u64 mem2[25];
    {
        const float* src = vmem + (size_t)(gb0 + bcol) * (MM * VV) + vcol;
        #pragma unroll
        for (int i = 0; i < 25; ++i)
            mem2[i] = pk2(src[(2 * i) * VV], src[(2 * i + 1) * VV]);
    }

    // ---- one-time setup ----
    for (int p = tid; p < VV * TWOA / 4; p += NTHR)
        ((float4*)(sh + OFF_WE))[p] = ((const float4*)We)[p];
    for (int p = tid; p < AA * VV; p += NTHR) {
        int a = p / VV, v = p % VV;
        sh[OFF_WR + a * 208 + v] = Wr[p];
    }
    for (int p = tid; p < AA; p += NTHR) sh[OFF_BR + p] = br[p];
    for (int p = tid; p < VV; p += NTHR) { sh[OFF_BE + p] = be[p]; sh[OFF_BA + p] = ba[p]; }
    if (tid < NB * KK) {
        int b = tid / KK, m = tid % KK;
        sh[OFF_W + b * 52 + m] = out[OUT_W + ((size_t)(gb0 + b) * SS) * MM + m];
    } else if (tid < NB * KK + NB * AA) {
        int i = tid - NB * KK;
        sh[OFF_AT + i] = att[((size_t)(gb0 + (i >> 6)) * SS) * AA + (i & 63)];
    }
    __syncthreads();

    // ---- hoisted prefetch pointer (one role per thread) ----
    const bool isW  = (tid < NB * KK);
    const bool isAT = (!isW) && (tid < NB * KK + NB * AA);
    const float* pfPtr = 0;
    int pfStride = 0;
    if (isW) {
        pfPtr = out + OUT_W + ((size_t)(gb0 + tid / KK) * SS + 1) * MM + tid % KK;
        pfStride = MM;
    } else if (isAT) {
        int i = tid - NB * KK;
        pfPtr = att + ((size_t)(gb0 + (i >> 6)) * SS + 1) * AA + (i & 63);
        pfStride = AA;
    }

    // ---- prologue: r(0) = w(0) . mem ----
    {
        const float4* w4 = (const float4*)(sh + OFF_W) + bcol * 13;
        u64 a0 = 0, a1 = 0;
        #pragma unroll
        for (int i = 0; i < 12; ++i) {
            F4U2 ww; ww.f = w4[i];
            a0 = ffma2(ww.u[0], mem2[2 * i],     a0);
            a1 = ffma2(ww.u[1], mem2[2 * i + 1], a1);
        }
        F4U2 wl; wl.f = w4[12];
        a0 = ffma2(wl.u[0], mem2[24], a0);
        u64 s2 = fadd2(a0, a1);
        sh[OFF_R + colOff] = unlo(s2) + unhi(s2);
    }
    __syncthreads();

    for (int t = 0; t < SS; ++t) {
        const int cur = t & 1, nxt = cur ^ 1;
        const bool last = (t == SS - 1);

        // ---- prefetch issue for t+1 ----
        float pf = 0.f;
        if (!last && (isW || isAT)) pf = *pfPtr;

        // ---- F: rc[b][a] = r[b].Wr[a] + br[a]; pair (wid, wid+25) ----
        {
            const float4* wrA = (const float4*)(sh + OFF_WR + wid * 208);
            const float4* wrB = wrA + 25 * 52;
            const float4* r4  = (const float4*)(sh + OFF_R);
            const bool l2 = (lane < 18);
            const float4 z = make_float4(0.f, 0.f, 0.f, 0.f);
            float a0, a1, a2, a3, b0, b1, b2, b3;
            {
                float4 x1 = wrA[lane];
                float4 x2 = wrB[lane];
                float4 r;
                r = r4[0 * 50 + lane]; a0 = dot4(x1, r, 0.f); b0 = dot4(x2, r, 0.f);
                r = r4[1 * 50 + lane]; a1 = dot4(x1, r, 0.f); b1 = dot4(x2, r, 0.f);
                r = r4[2 * 50 + lane]; a2 = dot4(x1, r, 0.f); b2 = dot4(x2, r, 0.f);
                r = r4[3 * 50 + lane]; a3 = dot4(x1, r, 0.f); b3 = dot4(x2, r, 0.f);
            }
            {
                float4 x1 = l2 ? wrA[32 + lane] : z;
                float4 x2 = l2 ? wrB[32 + lane] : z;
                float4 r;
                r = l2 ? r4[0 * 50 + 32 + lane] : z; a0 = dot4(x1, r, a0); b0 = dot4(x2, r, b0);
                r = l2 ? r4[1 * 50 + 32 + lane] : z; a1 = dot4(x1, r, a1); b1 = dot4(x2, r, b1);
                r = l2 ? r4[2 * 50 + 32 + lane] : z; a2 = dot4(x1, r, a2); b2 = dot4(x2, r, b2);
                r = l2 ? r4[3 * 50 + 32 + lane] : z; a3 = dot4(x1, r, a3); b3 = dot4(x2, r, b3);
            }
            float s = reduce8(a0, a1, a2, a3, b0, b1, b2, b3, lane);
            if (!(lane & 3)) {
                int idx = lane >> 2;                 // 0..7
                int b = idx & 3;
                int row = wid + ((idx & 4) ? 25 : 0);
                sh[OFF_RC + b * RCS + row] = s + sh[OFF_BR + row];
            }
            // singles: rows 50..63 for warps 0..13
            if (wid < 14) {
                int a = 50 + wid;
                const float4* wr4 = (const float4*)(sh + OFF_WR + a * 208);
                float4 x = wr4[lane];
                float4 y = l2 ? wr4[32 + lane] : z;
                float acc[NB];
                #pragma unroll
                for (int b = 0; b < NB; ++b) {
                    float4 ra = r4[b * 50 + lane];
                    float4 rb = l2 ? r4[b * 50 + 32 + lane] : z;
                    acc[b] = dot4(y, rb, dot4(x, ra, 0.f));
                }
                float s4 = reduce4(acc[0], acc[1], acc[2], acc[3], lane);
                if (!(lane & 7)) {
                    int b = lane >> 3;
                    sh[OFF_RC + b * RCS + a] = s4 + sh[OFF_BR + a];
                }
            }
        }
        __syncthreads();   // bar A

        // ---- rc out-store (address computed inline; no persistent pointer) ----
        if (tid < NB * AA) {
            out[OUT_RC + ((size_t)(gb0 + (tid >> 6)) * SS + t) * AA + (tid & 63)]
                = sh[OFF_RC + (tid >> 6) * RCS + (tid & 63)];
        }
        if (last) break;

        // ---- prefetch stores (overlap with gates) ----
        if (isW) {
            sh[OFF_W + (nxt * NB + tid / KK) * 52 + tid % KK] = pf;
            pfPtr += pfStride;
        } else if (isAT) {
            sh[OFF_AT + nxt * (NB * AA) + (tid - NB * KK)] = pf;
            pfPtr += pfStride;
        }

        // ---- G: merged gate matvecs (warp-per-row; We smem + Wa gmem) ----
        {
            float4 wi0, wi1, wi2, wi3;
            {
                const float4* at4 = (const float4*)(sh + OFF_AT + cur * (NB * AA));
                const float4* rc4 = (const float4*)(sh + OFF_RC);
                int lo = lane & 15;
                wi0 = (lane < 16) ? at4[0 * 16 + lo] : rc4[0 * 17 + lo];
                wi1 = (lane < 16) ? at4[1 * 16 + lo] : rc4[1 * 17 + lo];
                wi2 = (lane < 16) ? at4[2 * 16 + lo] : rc4[2 * 17 + lo];
                wi3 = (lane < 16) ? at4[3 * 16 + lo] : rc4[3 * 17 + lo];
            }
            #pragma unroll 4
            for (int r8 = 0; r8 < 8; ++r8) {
                int v = wid + 25 * r8;
                float4 wa = ((const float4*)(Wa + v * TWOA))[lane];   // LDG early
                float4 we = ((const float4*)(sh + OFF_WE + v * TWOA))[lane];
                float e0 = dot4(we, wi0, 0.f);
                float e1 = dot4(we, wi1, 0.f);
                float e2 = dot4(we, wi2, 0.f);
                float e3 = dot4(we, wi3, 0.f);
                float g0 = dot4(wa, wi0, 0.f);
                float g1 = dot4(wa, wi1, 0.f);
                float g2 = dot4(wa, wi2, 0.f);
                float g3 = dot4(wa, wi3, 0.f);
                float s = reduce8(e0, e1, e2, e3, g0, g1, g2, g3, lane);
                if (!(lane & 3)) {
                    int idx = lane >> 2;
                    int b = idx & 3;
                    sh[((idx & 4) ? OFF_AR : OFF_ER) + b * VV + v] = s;
                }
            }
        }
        __syncthreads();   // bar B

        // ---- fused H+E (packed f32x2): update with w(t), read with w(t+1) ----
        {
            float re = sh[OFF_ER + colOff] + sh[OFF_BE + vcol];
            float ra = sh[OFF_AR + colOff] + sh[OFF_BA + vcol];
            float er = 1.f / (1.f + __expf(-re));          // sigmoid
            float ea = __expf(2.f * ra);
            float ad = 1.f - 2.f / (ea + 1.f);             // tanh

            u64 nEr2 = pk2(-er, -er);
            u64 ad2  = pk2(ad, ad);

            const float4* wc4 = (const float4*)(sh + OFF_W) + (cur * NB + bcol) * 13;
            const float4* wn4 = (const float4*)(sh + OFF_W) + (nxt * NB + bcol) * 13;
            u64 a0 = 0, a1 = 0;
            #pragma unroll
            for (int i = 0; i < 12; ++i) {
                F4U2 wc; wc.f = wc4[i];
                F4U2 wn; wn.f = wn4[i];
                u64 m0 = mem2[2 * i];
                u64 m1 = mem2[2 * i + 1];
                m0 = ffma2(wc.u[0], ffma2(nEr2, m0, ad2), m0);
                m1 = ffma2(wc.u[1], ffma2(nEr2, m1, ad2), m1);
                a0 = ffma2(wn.u[0], m0, a0);
                a1 = ffma2(wn.u[1], m1, a1);
                mem2[2 * i]     = m0;
                mem2[2 * i + 1] = m1;
            }
            F4U2 wcl; wcl.f = wc4[12];
            F4U2 wnl; wnl.f = wn4[12];
            u64 m = mem2[24];
            m = ffma2(wcl.u[0], ffma2(nEr2, m, ad2), m);
            a0 = ffma2(wnl.u[0], m, a0);
            mem2[24] = m;
            u64 s2 = fadd2(a0, a1);
            sh[OFF_R + colOff] = unlo(s2) + unhi(s2);
        }
        __syncthreads();   // bar C
    }

    // ---- final memory state ----
    {
        float* dst = out + OUT_MEM + (size_t)(gb0 + bcol) * (MM * VV) + vcol;
        #pragma unroll
        for (int i = 0; i < 25; ++i) {
            dst[(2 * i) * VV]     = unlo(mem2[i]);
            dst[(2 * i + 1) * VV] = unhi(mem2[i]);
        }
    }
}

extern "C" void kernel_launch(void* const* d_in, const int* in_sizes, int n_in,
                              void* d_out, int out_size)
{
    (void)in_sizes; (void)n_in; (void)out_size;
    const float* q_emb = (const float*)d_in[0];
    const float* att   = (const float*)d_in[1];
    const float* vmem  = (const float*)d_in[2];
    const float* km    = (const float*)d_in[3];
    const float* Wc    = (const float*)d_in[4];
    const float* bc    = (const float*)d_in[5];
    const float* Wr    = (const float*)d_in[6];
    const float* br    = (const float*)d_in[7];
    const float* We    = (const float*)d_in[8];
    const float* be    = (const float*)d_in[9];
    const float* Wa    = (const float*)d_in[10];
    const float* ba    = (const float*)d_in[11];
    float* out = (float*)d_out;

    cudaFuncSetAttribute(agm_recur_kernel,
                         cudaFuncAttributeMaxDynamicSharedMemorySize,
                         SMEM2_BYTES);

    agm_weights_kernel<<<K1_GRID, K1_THREADS>>>(q_emb, km, Wc, bc, out);
    agm_recur_kernel<<<NBLK, NTHR, SMEM2_BYTES>>>(att, vmem, Wr, br,
                                                  We, be, Wa, ba, out);
}